// round 8
// baseline (speedup 1.0000x reference)
#include <cuda_runtime.h>
#include <math.h>
#include <stdint.h>

// Problem constants
#define B 8
#define A 100000
#define M 32
#define C 80
#define APB 320                      // anchors per block = threads (multiple of 20!)
#define NTILES ((A + APB - 1) / APB) // 313
#define NBLK (NTILES * B)            // 2504
#define V4PA (C / 4)                 // float4 per anchor = 20

// mask weight for contributing anchors: -0.75 * ln(2)
#define NEGW (-0.5198603854199589f)

// Per-CTA partials + finalize ticket (device globals; no allocation allowed)
__device__ float g_cls_part[NBLK];
__device__ float g_reg_part[NBLK];
__device__ int   g_pos_part[NBLK];
__device__ unsigned int g_ticket = 0;

// min-blocks=3 raises the per-thread register budget to ~68 so ptxas can keep
// 10 LDG.128 in flight (MLP ~10) instead of collapsing to 2-deep load-use.
__global__ __launch_bounds__(APB, 3) void fl_fused_kernel(
    const float* __restrict__ cls,      // [B, A, C]
    const float* __restrict__ reg,      // [B, A, 4]
    const float* __restrict__ anchors,  // [1, A, 4]
    const float* __restrict__ ann,      // [B, M, 6]
    float* __restrict__ out)            // [2]
{
    __shared__ float4 s_box[M];          // gt box x1,y1,x2,y2 (invalid -> far away)
    __shared__ float2 s_misc[M];         // x = area_b, y = class id
    __shared__ float  s_mask[APB];       // NEGW if anchor contributes, else 0
    __shared__ float  s_rc[APB / 32];
    __shared__ float  s_rr[APB / 32];
    __shared__ int    s_rp[APB / 32];
    __shared__ bool   s_last;

    const int b    = blockIdx.y;
    const int a0   = blockIdx.x * APB;
    const int tid  = threadIdx.x;
    const int blk  = b * NTILES + blockIdx.x;

    if (tid < M) {
        const float* ap = ann + (b * M + tid) * 6;
        float x1 = ap[0], y1 = ap[1], x2 = ap[2], y2 = ap[3];
        const float cl = ap[4];
        float area = (x2 - x1) * (y2 - y1);
        if (cl == -1.0f) {
            // Invalid GT: far-away box -> inter == 0 for every anchor, area 0
            // -> identical classification/argmax behavior to reference's -1.
            x1 = 3e9f; y1 = 3e9f; x2 = 3e9f; y2 = 3e9f; area = 0.0f;
        }
        s_box[tid]  = make_float4(x1, y1, x2, y2);
        s_misc[tid] = make_float2(area, cl);
    }
    __syncthreads();

    float reg_partial = 0.0f;
    float cls_partial = 0.0f;
    int   pos_cnt = 0;

    const int a = a0 + tid;
    if (a < A) {
        const float4 av = *reinterpret_cast<const float4*>(anchors + a * 4);
        const float ax1 = av.x, ay1 = av.y, ax2 = av.z, ay2 = av.w;
        const float aw = ax2 - ax1;
        const float ah = ay2 - ay1;
        const float area_a = aw * ah;

        // IoU argmax via cross-multiplication (no division; ua >= area_a > 0).
        float b_in = -1.0f, b_ua = 1.0f;
        int   bi = 0;
        #pragma unroll 8
        for (int j = 0; j < M; j++) {
            const float4 g  = s_box[j];
            const float2 mi = s_misc[j];
            const float iw = fminf(ax2, g.z) - fmaxf(ax1, g.x);
            const float ih = fminf(ay2, g.w) - fmaxf(ay1, g.y);
            const float inter = fmaxf(iw, 0.0f) * fmaxf(ih, 0.0f);
            const float ua = (area_a + mi.x) - inter;
            const bool upd = (inter * b_ua > b_in * ua);
            if (upd) { b_in = inter; b_ua = ua; bi = j; }
        }

        const bool pos = (b_in >= 0.5f * b_ua);
        const bool ign = (!pos) && (b_in >= 0.4f * b_ua);
        s_mask[tid] = ign ? 0.0f : NEGW;

        if (pos) {
            pos_cnt = 1;
            const float4 g = s_box[bi];

            // positive-class correction: remove exactly what phase 2 adds,
            // add the reference positive term.
            const int cid = (int)s_misc[bi].y;
            const float p_raw = cls[((size_t)b * A + a) * C + cid];
            const float phase2_term =
                NEGW * (p_raw * p_raw * __log2f(1.0f - p_raw));
            const float pc = fminf(fmaxf(p_raw, 1e-4f), 1.0f - 1e-4f);
            const float qc = 1.0f - pc;
            cls_partial += 0.25f * qc * qc * (-__logf(pc)) - phase2_term;

            // regression loss (smooth L1)
            float gw = g.z - g.x;
            float gh = g.w - g.y;
            const float gcx = g.x + 0.5f * gw;
            const float gcy = g.y + 0.5f * gh;
            gw = fmaxf(gw, 1.0f);
            gh = fmaxf(gh, 1.0f);
            const float acx = ax1 + 0.5f * aw;
            const float acy = ay1 + 0.5f * ah;

            const float t0 = ((gcx - acx) / aw) * 10.0f;
            const float t1 = ((gcy - acy) / ah) * 10.0f;
            const float t2 = __logf(gw / aw) * 5.0f;
            const float t3 = __logf(gh / ah) * 5.0f;

            const float4 r = *reinterpret_cast<const float4*>(reg + ((size_t)b * A + a) * 4);
            const float d0 = fabsf(t0 - r.x);
            const float d1 = fabsf(t1 - r.y);
            const float d2 = fabsf(t2 - r.z);
            const float d3 = fabsf(t3 - r.w);
            const float th = 1.0f / 9.0f;
            const float c2 = 0.5f / 9.0f;
            float rl = 0.0f;
            rl += (d0 <= th) ? 4.5f * d0 * d0 : d0 - c2;
            rl += (d1 <= th) ? 4.5f * d1 * d1 : d1 - c2;
            rl += (d2 <= th) ? 4.5f * d2 * d2 : d2 - c2;
            rl += (d3 <= th) ? 4.5f * d3 * d3 : d3 - c2;
            reg_partial = rl;
        }
    } else {
        s_mask[tid] = 0.0f;
    }
    __syncthreads();

    // Phase 2: 2 mega-groups of 10 outstanding LDG.128 each (MLP ~10).
    // APB = 320 = 16*20 -> anchor(tid + 320k) = tid/20 + 16k.
    {
        const int nA = min(APB, A - a0);
        const float4* __restrict__ cp4 =
            reinterpret_cast<const float4*>(cls + ((size_t)b * A + a0) * C);
        const int mbase = tid / 20;

        float acc0 = 0.f, acc1 = 0.f, acc2 = 0.f, acc3 = 0.f, acc4 = 0.f;

        // s = sum_i p_i^2 * log2(1 - p_i), FMA-chained, no clamps
        #define NT4S(v, s)                                                       \
        {                                                                        \
            const float l0 = __log2f(1.0f - (v).x);                              \
            const float l1 = __log2f(1.0f - (v).y);                              \
            const float l2 = __log2f(1.0f - (v).z);                              \
            const float l3 = __log2f(1.0f - (v).w);                              \
            const float q0 = (v).x * (v).x;                                      \
            const float q1 = (v).y * (v).y;                                      \
            const float q2 = (v).z * (v).z;                                      \
            const float q3 = (v).w * (v).w;                                      \
            s = fmaf(q0, l0, fmaf(q1, l1, fmaf(q2, l2, q3 * l3)));               \
        }

        if (nA == APB) {
            #define FL_GROUP10(gbase)                                            \
            {                                                                    \
                const float4 v0 = __ldcs(cp4 + (tid + (gbase + 0) * APB));       \
                const float4 v1 = __ldcs(cp4 + (tid + (gbase + 1) * APB));       \
                const float4 v2 = __ldcs(cp4 + (tid + (gbase + 2) * APB));       \
                const float4 v3 = __ldcs(cp4 + (tid + (gbase + 3) * APB));       \
                const float4 v4 = __ldcs(cp4 + (tid + (gbase + 4) * APB));       \
                const float4 v5 = __ldcs(cp4 + (tid + (gbase + 5) * APB));       \
                const float4 v6 = __ldcs(cp4 + (tid + (gbase + 6) * APB));       \
                const float4 v7 = __ldcs(cp4 + (tid + (gbase + 7) * APB));       \
                const float4 v8 = __ldcs(cp4 + (tid + (gbase + 8) * APB));       \
                const float4 v9 = __ldcs(cp4 + (tid + (gbase + 9) * APB));       \
                const float m0 = s_mask[mbase + 16 * (gbase + 0)];               \
                const float m1 = s_mask[mbase + 16 * (gbase + 1)];               \
                const float m2 = s_mask[mbase + 16 * (gbase + 2)];               \
                const float m3 = s_mask[mbase + 16 * (gbase + 3)];               \
                const float m4 = s_mask[mbase + 16 * (gbase + 4)];               \
                const float m5 = s_mask[mbase + 16 * (gbase + 5)];               \
                const float m6 = s_mask[mbase + 16 * (gbase + 6)];               \
                const float m7 = s_mask[mbase + 16 * (gbase + 7)];               \
                const float m8 = s_mask[mbase + 16 * (gbase + 8)];               \
                const float m9 = s_mask[mbase + 16 * (gbase + 9)];               \
                float s0, s1, s2, s3, s4, s5, s6, s7, s8, s9;                    \
                NT4S(v0, s0) NT4S(v1, s1) NT4S(v2, s2) NT4S(v3, s3) NT4S(v4, s4) \
                NT4S(v5, s5) NT4S(v6, s6) NT4S(v7, s7) NT4S(v8, s8) NT4S(v9, s9) \
                acc0 = fmaf(m0, s0, acc0);                                       \
                acc1 = fmaf(m1, s1, acc1);                                       \
                acc2 = fmaf(m2, s2, acc2);                                       \
                acc3 = fmaf(m3, s3, acc3);                                       \
                acc4 = fmaf(m4, s4, acc4);                                       \
                acc0 = fmaf(m5, s5, acc0);                                       \
                acc1 = fmaf(m6, s6, acc1);                                       \
                acc2 = fmaf(m7, s7, acc2);                                       \
                acc3 = fmaf(m8, s8, acc3);                                       \
                acc4 = fmaf(m9, s9, acc4);                                       \
            }
            FL_GROUP10(0)
            FL_GROUP10(10)
            #undef FL_GROUP10
        } else {
            const int n4 = nA * V4PA;
            for (int k = 0; k < V4PA; k++) {
                const int i4 = tid + k * APB;
                if (i4 < n4) {
                    const float4 v = __ldcs(cp4 + i4);
                    const float m = s_mask[mbase + 16 * k];
                    float s;
                    NT4S(v, s)
                    acc0 = fmaf(m, s, acc0);
                }
            }
        }
        #undef NT4S
        cls_partial += ((acc0 + acc1) + (acc2 + acc3)) + acc4;
    }

    // Block reduction -> per-CTA partials
    float cv = cls_partial;
    float rv = reg_partial;
    int   pv = pos_cnt;
    #pragma unroll
    for (int o = 16; o > 0; o >>= 1) {
        cv += __shfl_down_sync(0xFFFFFFFFu, cv, o);
        rv += __shfl_down_sync(0xFFFFFFFFu, rv, o);
        pv += __shfl_down_sync(0xFFFFFFFFu, pv, o);
    }
    const int wid = tid >> 5;
    const int lane = tid & 31;
    if (lane == 0) { s_rc[wid] = cv; s_rr[wid] = rv; s_rp[wid] = pv; }
    __syncthreads();

    if (tid == 0) {
        float c = 0.0f, r = 0.0f;
        int p = 0;
        #pragma unroll
        for (int i = 0; i < APB / 32; i++) { c += s_rc[i]; r += s_rr[i]; p += s_rp[i]; }
        g_cls_part[blk] = c;
        g_reg_part[blk] = r;
        g_pos_part[blk] = p;
        __threadfence();
        const unsigned int t = atomicAdd(&g_ticket, 1u);
        s_last = (t == (unsigned int)(NBLK - 1));
    }
    __syncthreads();

    // Last CTA reduces all per-CTA partials and writes the output.
    if (s_last) {
        __shared__ double f_c[B][APB / 32];
        __shared__ double f_r[B][APB / 32];
        __shared__ int    f_p[B][APB / 32];

        #pragma unroll
        for (int img = 0; img < B; img++) {
            double c = 0.0, r = 0.0;
            int p = 0;
            for (int i = tid; i < NTILES; i += APB) {
                const int idx = img * NTILES + i;
                c += (double)g_cls_part[idx];
                r += (double)g_reg_part[idx];
                p += g_pos_part[idx];
            }
            #pragma unroll
            for (int o = 16; o > 0; o >>= 1) {
                c += __shfl_down_sync(0xFFFFFFFFu, c, o);
                r += __shfl_down_sync(0xFFFFFFFFu, r, o);
                p += __shfl_down_sync(0xFFFFFFFFu, p, o);
            }
            if (lane == 0) { f_c[img][wid] = c; f_r[img][wid] = r; f_p[img][wid] = p; }
        }
        __syncthreads();
        if (tid == 0) {
            double cl = 0.0, rl = 0.0;
            #pragma unroll
            for (int img = 0; img < B; img++) {
                double c = 0.0, r = 0.0;
                int p = 0;
                #pragma unroll
                for (int i = 0; i < APB / 32; i++) {
                    c += f_c[img][i]; r += f_r[img][i]; p += f_p[img][i];
                }
                const double d = (p < 1) ? 1.0 : (double)p;
                cl += c / d;
                if (p > 0) rl += r / (4.0 * d);
            }
            out[0] = (float)(cl / (double)B);
            out[1] = (float)(rl / (double)B);
            g_ticket = 0;  // reset for the next graph replay
        }
    }
}

extern "C" void kernel_launch(void* const* d_in, const int* in_sizes, int n_in,
                              void* d_out, int out_size) {
    const float* cls = nullptr;
    const float* reg = nullptr;
    const float* anc = nullptr;
    const float* ann = nullptr;
    for (int i = 0; i < n_in; i++) {
        switch (in_sizes[i]) {
            case B * A * C:  cls = (const float*)d_in[i]; break;  // 64,000,000
            case B * A * 4:  reg = (const float*)d_in[i]; break;  //  3,200,000
            case A * 4:      anc = (const float*)d_in[i]; break;  //    400,000
            case B * M * 6:  ann = (const float*)d_in[i]; break;  //      1,536
            default: break;
        }
    }
    float* out = (float*)d_out;

    dim3 grid(NTILES, B);
    fl_fused_kernel<<<grid, APB>>>(cls, reg, anc, ann, out);
}